// round 5
// baseline (speedup 1.0000x reference)
#include <cuda_runtime.h>

#define B   128
#define M   200
#define S   20
#define D   128
#define NC  10000
#define CL  10
#define HOPS 3

// Scratch (no cudaMalloc allowed)
__device__ float g_m[B * M * D];      // 13.1 MB: memory encodings
__device__ float g_u[B * D];          // query state (b-major, hops input)
__device__ float g_uT[D * B];         // query state transposed (gemm A operand)
__device__ float g_cand[NC * D];      // candidate sums

// ---------------------------------------------------------------------------
// Kernel 1 (fused gathers): three independent block ranges in one grid so the
// A-table and W-table gather traffic overlaps instead of serializing.
//   blocks [0, B*M)            : m[b,mm,:] = sum_s A[stories[b,mm,s]]
//   blocks [B*M, B*M+B)        : u[b,:]    = sum_s A[queries[b,s]]
//   blocks [B*M+B, ... +NC)    : cand[c,:] = sum_l W[candidates[c,l]]
// 128 threads; thread t owns column t; rows are 512B coalesced gathers.
// padding_idx=0 rows are skipped (zero).
// ---------------------------------------------------------------------------
__global__ void gather_all_kernel(const int* __restrict__ stories,
                                  const int* __restrict__ queries,
                                  const int* __restrict__ candidates,
                                  const float* __restrict__ A,
                                  const float* __restrict__ W) {
    __shared__ int sidx[S];
    const int bi = blockIdx.x;
    const int t  = threadIdx.x;

    if (bi < B * M) {
        if (t < S) sidx[t] = stories[(size_t)bi * S + t];
        __syncthreads();
        float acc = 0.f;
#pragma unroll
        for (int s = 0; s < S; s++) {
            int idx = sidx[s];
            if (idx != 0) acc += A[(size_t)idx * D + t];
        }
        g_m[(size_t)bi * D + t] = acc;
    } else if (bi < B * M + B) {
        const int b = bi - B * M;
        if (t < S) sidx[t] = queries[b * S + t];
        __syncthreads();
        float acc = 0.f;
#pragma unroll
        for (int s = 0; s < S; s++) {
            int idx = sidx[s];
            if (idx != 0) acc += A[(size_t)idx * D + t];
        }
        g_u[b * D + t] = acc;
    } else {
        const int c = bi - (B * M + B);
        if (t < CL) sidx[t] = candidates[(size_t)c * CL + t];
        __syncthreads();
        float acc = 0.f;
#pragma unroll
        for (int l = 0; l < CL; l++) {
            int idx = sidx[l];
            if (idx != 0) acc += W[(size_t)idx * D + t];
        }
        g_cand[(size_t)c * D + t] = acc;
    }
}

// ---------------------------------------------------------------------------
// Kernel 2: 3 attention hops, one block per batch element.
// m[b] (100KB) + H_w (pitch 129, 64.5KB) staged in smem once, reused 3 hops.
// Epilogue writes u transposed for the GEMM.
// ---------------------------------------------------------------------------
#define HW_PITCH 129
#define HOP_THREADS 256

__global__ void hops_kernel(const float* __restrict__ Hw) {
    extern __shared__ float smem[];
    float* sm_m   = smem;                        // M*D
    float* sm_h   = sm_m + M * D;                // D*HW_PITCH
    float* sm_u   = sm_h + D * HW_PITCH;         // D
    float* sm_dot = sm_u + D;                    // M
    float* sm_red = sm_dot + M;                  // HOP_THREADS

    const int b  = blockIdx.x;
    const int t  = threadIdx.x;

    {
        const float4* gm4 = (const float4*)(g_m + (size_t)b * M * D);
        float4* sm4 = (float4*)sm_m;
        for (int i = t; i < M * D / 4; i += HOP_THREADS) sm4[i] = gm4[i];
        for (int i = t; i < D * D; i += HOP_THREADS) {
            int d = i >> 7, k = i & 127;
            sm_h[d * HW_PITCH + k] = Hw[i];
        }
        if (t < D) sm_u[t] = g_u[b * D + t];
    }
    __syncthreads();

    const int warp = t >> 5, lane = t & 31;

    for (int hop = 0; hop < HOPS; hop++) {
        // dotted[mm] = <m[mm], u>
        for (int mm = warp; mm < M; mm += HOP_THREADS / 32) {
            const float* row = sm_m + mm * D;
            float s = 0.f;
#pragma unroll
            for (int k = lane; k < D; k += 32) s += row[k] * sm_u[k];
#pragma unroll
            for (int off = 16; off; off >>= 1)
                s += __shfl_xor_sync(0xffffffffu, s, off);
            if (lane == 0) sm_dot[mm] = s;
        }
        __syncthreads();

        // softmax over M
        float lm = -1e30f;
        for (int i = t; i < M; i += HOP_THREADS) lm = fmaxf(lm, sm_dot[i]);
        sm_red[t] = lm; __syncthreads();
        for (int s = HOP_THREADS / 2; s > 0; s >>= 1) {
            if (t < s) sm_red[t] = fmaxf(sm_red[t], sm_red[t + s]);
            __syncthreads();
        }
        const float mx = sm_red[0];
        __syncthreads();

        float ls = 0.f;
        for (int i = t; i < M; i += HOP_THREADS) {
            float e = __expf(sm_dot[i] - mx);
            sm_dot[i] = e;
            ls += e;
        }
        sm_red[t] = ls; __syncthreads();
        for (int s = HOP_THREADS / 2; s > 0; s >>= 1) {
            if (t < s) sm_red[t] += sm_red[t + s];
            __syncthreads();
        }
        const float inv = 1.f / sm_red[0];
        __syncthreads();

        // o[d] = inv * sum_mm e[mm]*m[mm][d];  u = tanh(Hw @ u + o)
        float unew = 0.f;
        if (t < D) {
            float o = 0.f;
            for (int mm = 0; mm < M; mm++)
                o += sm_dot[mm] * sm_m[mm * D + t];
            o *= inv;
            float h = 0.f;
            const float* hr = sm_h + t * HW_PITCH;
#pragma unroll 8
            for (int k = 0; k < D; k++) h += hr[k] * sm_u[k];
            unew = tanhf(h + o);
        }
        __syncthreads();
        if (t < D) sm_u[t] = unew;
        __syncthreads();
    }
    if (t < D) g_uT[t * B + b] = sm_u[t];   // transposed for GEMM A-stage
}

// ---------------------------------------------------------------------------
// Kernel 3: logits[b,c] = <u[b], cand_sum[c]>.  128x10000, K=128.
// 64x64 tiles (grid 157x2 = 314 blocks), 70KB smem -> 3 CTAs/SM capacity,
// balanced 2-3 CTAs/SM. Per-thread 4x4 register tile: 2xLDS.128 + 16 FFMA/k.
// ---------------------------------------------------------------------------
#define BMT 64
#define BNT 64
#define KP  68    // smem pitch (floats): mult of 4 (float4), not mult of 32

__global__ void gemm_kernel(float* __restrict__ out) {
    extern __shared__ float sm[];
    float* su = sm;             // su[k*KP + b]  (A frag, k-major)
    float* sc = sm + D * KP;    // sc[k*KP + c]  (B frag, k-major)
    const int t = threadIdx.x;
    const int cbase = blockIdx.x * BNT;
    const int bbase = blockIdx.y * BMT;

    // stage A from transposed u: coalesced read, conflict-free smem write
    for (int i = t; i < BMT * D; i += 256) {
        int k = i >> 6, b = i & 63;
        su[k * KP + b] = g_uT[k * B + bbase + b];
    }
    // stage B (transpose in smem; 4-way write conflicts, negligible volume)
    for (int i = t; i < BNT * D; i += 256) {
        int c = i >> 7, k = i & 127;
        int gc = cbase + c;
        sc[k * KP + c] = (gc < NC) ? g_cand[(size_t)gc * D + k] : 0.f;
    }
    __syncthreads();

    const int tx = t & 15, ty = t >> 4;
    const int b0 = ty * 4, c0 = tx * 4;
    float acc[4][4] = {};

#pragma unroll 8
    for (int k = 0; k < D; k++) {
        float4 a  = *(const float4*)&su[k * KP + b0];
        float4 v  = *(const float4*)&sc[k * KP + c0];
        float av[4] = {a.x, a.y, a.z, a.w};
        float vv[4] = {v.x, v.y, v.z, v.w};
#pragma unroll
        for (int i = 0; i < 4; i++)
#pragma unroll
            for (int j = 0; j < 4; j++) acc[i][j] += av[i] * vv[j];
    }

#pragma unroll
    for (int i = 0; i < 4; i++) {
        const int b = bbase + b0 + i;
        const int gc = cbase + c0;
        if (gc + 3 < NC) {
            *(float4*)&out[(size_t)b * NC + gc] =
                make_float4(acc[i][0], acc[i][1], acc[i][2], acc[i][3]);
        } else {
#pragma unroll
            for (int q = 0; q < 4; q++)
                if (gc + q < NC) out[(size_t)b * NC + gc + q] = acc[i][q];
        }
    }
}

// ---------------------------------------------------------------------------
extern "C" void kernel_launch(void* const* d_in, const int* in_sizes, int n_in,
                              void* d_out, int out_size) {
    const int*   stories    = (const int*)d_in[0];
    const int*   queries    = (const int*)d_in[1];
    const int*   candidates = (const int*)d_in[2];
    const float* A_tab      = (const float*)d_in[3];
    const float* W_tab      = (const float*)d_in[4];
    const float* H_w        = (const float*)d_in[5];
    float*       out        = (float*)d_out;

    const int hops_smem = (M * D + D * HW_PITCH + D + M + HOP_THREADS) * sizeof(float);
    const int gemm_smem = 2 * D * KP * sizeof(float);
    cudaFuncSetAttribute(hops_kernel, cudaFuncAttributeMaxDynamicSharedMemorySize, hops_smem);
    cudaFuncSetAttribute(gemm_kernel, cudaFuncAttributeMaxDynamicSharedMemorySize, gemm_smem);

    gather_all_kernel<<<B * M + B + NC, 128>>>(stories, queries, candidates, A_tab, W_tab);
    hops_kernel<<<B, HOP_THREADS, hops_smem>>>(H_w);

    dim3 ggrid((NC + BNT - 1) / BNT, B / BMT);   // 157 x 2
    gemm_kernel<<<ggrid, 256, gemm_smem>>>(out);
}

// round 6
// speedup vs baseline: 1.7007x; 1.7007x over previous
#include <cuda_runtime.h>

#define B   128
#define M   200
#define S   20
#define D   128
#define NC  10000
#define CL  10
#define HOPS 3

// Scratch (no cudaMalloc allowed)
__device__ float g_m[B * M * D];      // 13.1 MB: memory encodings
__device__ float g_u[B * D];          // query state (b-major, hops input)
__device__ float g_uT[D * B];         // query state transposed (gemm A operand)
__device__ float g_cand[NC * D];      // candidate sums

// ---------------------------------------------------------------------------
// Kernel 1: warp-per-row gathers. Lane l owns float4 column 4l (warp = 512B
// row). Indices lane-loaded then shfl-broadcast (warp-uniform -> uniform
// branch on padding idx 0). Fully unrolled -> ptxas batches the independent
// LDG.128s (high MLP), 4x fewer load instructions than thread-per-scalar.
//   rows [0, B*M)        : m[row,:]  = sum_s A[stories[row,s]]
//   rows [B*M, B*M+B)    : u[b,:]    = sum_s A[queries[b,s]]
//   rows [B*M+B, +NC)    : cand[c,:] = sum_l W[candidates[c,l]]
// ---------------------------------------------------------------------------
#define ROWS_TOTAL (B * M + B + NC)

template <int N>
__device__ __forceinline__ void gather_row(const int* __restrict__ idxp,
                                           const float* __restrict__ tab,
                                           float* __restrict__ dst,
                                           int lane) {
    int myidx = (lane < N) ? idxp[lane] : 0;
    float4 acc = make_float4(0.f, 0.f, 0.f, 0.f);
#pragma unroll
    for (int s = 0; s < N; s++) {
        int idx = __shfl_sync(0xffffffffu, myidx, s);
        if (idx != 0) {
            float4 v = *(const float4*)(tab + (size_t)idx * D + lane * 4);
            acc.x += v.x; acc.y += v.y; acc.z += v.z; acc.w += v.w;
        }
    }
    *(float4*)(dst + lane * 4) = acc;
}

__global__ void gather_all_kernel(const int* __restrict__ stories,
                                  const int* __restrict__ queries,
                                  const int* __restrict__ candidates,
                                  const float* __restrict__ A,
                                  const float* __restrict__ W) {
    const int row  = (blockIdx.x * blockDim.x + threadIdx.x) >> 5;
    const int lane = threadIdx.x & 31;
    if (row >= ROWS_TOTAL) return;

    if (row < B * M) {
        gather_row<S>(stories + (size_t)row * S, A, g_m + (size_t)row * D, lane);
    } else if (row < B * M + B) {
        const int b = row - B * M;
        gather_row<S>(queries + (size_t)b * S, A, g_u + (size_t)b * D, lane);
    } else {
        const int c = row - (B * M + B);
        gather_row<CL>(candidates + (size_t)c * CL, W, g_cand + (size_t)c * D, lane);
    }
}

// ---------------------------------------------------------------------------
// Kernel 2: 3 attention hops, one block per batch element.
// m[b] (100KB) + H_w (pitch 129, 64.5KB) staged in smem once, reused 3 hops.
// Epilogue writes u transposed for the GEMM.
// ---------------------------------------------------------------------------
#define HW_PITCH 129
#define HOP_THREADS 256

__global__ void hops_kernel(const float* __restrict__ Hw) {
    extern __shared__ float smem[];
    float* sm_m   = smem;                        // M*D
    float* sm_h   = sm_m + M * D;                // D*HW_PITCH
    float* sm_u   = sm_h + D * HW_PITCH;         // D
    float* sm_dot = sm_u + D;                    // M
    float* sm_red = sm_dot + M;                  // HOP_THREADS

    const int b  = blockIdx.x;
    const int t  = threadIdx.x;

    {
        const float4* gm4 = (const float4*)(g_m + (size_t)b * M * D);
        float4* sm4 = (float4*)sm_m;
        for (int i = t; i < M * D / 4; i += HOP_THREADS) sm4[i] = gm4[i];
        for (int i = t; i < D * D; i += HOP_THREADS) {
            int d = i >> 7, k = i & 127;
            sm_h[d * HW_PITCH + k] = Hw[i];
        }
        if (t < D) sm_u[t] = g_u[b * D + t];
    }
    __syncthreads();

    const int warp = t >> 5, lane = t & 31;

    for (int hop = 0; hop < HOPS; hop++) {
        // dotted[mm] = <m[mm], u>
        for (int mm = warp; mm < M; mm += HOP_THREADS / 32) {
            const float* row = sm_m + mm * D;
            float s = 0.f;
#pragma unroll
            for (int k = lane; k < D; k += 32) s += row[k] * sm_u[k];
#pragma unroll
            for (int off = 16; off; off >>= 1)
                s += __shfl_xor_sync(0xffffffffu, s, off);
            if (lane == 0) sm_dot[mm] = s;
        }
        __syncthreads();

        // softmax over M
        float lm = -1e30f;
        for (int i = t; i < M; i += HOP_THREADS) lm = fmaxf(lm, sm_dot[i]);
        sm_red[t] = lm; __syncthreads();
        for (int s = HOP_THREADS / 2; s > 0; s >>= 1) {
            if (t < s) sm_red[t] = fmaxf(sm_red[t], sm_red[t + s]);
            __syncthreads();
        }
        const float mx = sm_red[0];
        __syncthreads();

        float ls = 0.f;
        for (int i = t; i < M; i += HOP_THREADS) {
            float e = __expf(sm_dot[i] - mx);
            sm_dot[i] = e;
            ls += e;
        }
        sm_red[t] = ls; __syncthreads();
        for (int s = HOP_THREADS / 2; s > 0; s >>= 1) {
            if (t < s) sm_red[t] += sm_red[t + s];
            __syncthreads();
        }
        const float inv = 1.f / sm_red[0];
        __syncthreads();

        // o[d] = inv * sum_mm e[mm]*m[mm][d];  u = tanh(Hw @ u + o)
        float unew = 0.f;
        if (t < D) {
            float o = 0.f;
            for (int mm = 0; mm < M; mm++)
                o += sm_dot[mm] * sm_m[mm * D + t];
            o *= inv;
            float h = 0.f;
            const float* hr = sm_h + t * HW_PITCH;
#pragma unroll 8
            for (int k = 0; k < D; k++) h += hr[k] * sm_u[k];
            unew = tanhf(h + o);
        }
        __syncthreads();
        if (t < D) sm_u[t] = unew;
        __syncthreads();
    }
    if (t < D) g_uT[t * B + b] = sm_u[t];   // transposed for GEMM A-stage
}

// ---------------------------------------------------------------------------
// Kernel 3: logits[b,c] = <u[b], cand_sum[c]>.  128x10000, K=128.
// 64x64 tiles (grid 157x2 = 314 blocks), 70KB smem -> 3 CTAs/SM capacity.
// Per-thread 4x4 register tile: 2xLDS.128 + 16 FFMA per k.
// ---------------------------------------------------------------------------
#define BMT 64
#define BNT 64
#define KP  68    // smem pitch (floats): mult of 4 (float4), not mult of 32

__global__ void gemm_kernel(float* __restrict__ out) {
    extern __shared__ float sm[];
    float* su = sm;             // su[k*KP + b]  (A frag, k-major)
    float* sc = sm + D * KP;    // sc[k*KP + c]  (B frag, k-major)
    const int t = threadIdx.x;
    const int cbase = blockIdx.x * BNT;
    const int bbase = blockIdx.y * BMT;

    // stage A from transposed u: coalesced read, conflict-free smem write
    for (int i = t; i < BMT * D; i += 256) {
        int k = i >> 6, b = i & 63;
        su[k * KP + b] = g_uT[k * B + bbase + b];
    }
    // stage B (transpose in smem)
    for (int i = t; i < BNT * D; i += 256) {
        int c = i >> 7, k = i & 127;
        int gc = cbase + c;
        sc[k * KP + c] = (gc < NC) ? g_cand[(size_t)gc * D + k] : 0.f;
    }
    __syncthreads();

    const int tx = t & 15, ty = t >> 4;
    const int b0 = ty * 4, c0 = tx * 4;
    float acc[4][4] = {};

#pragma unroll 8
    for (int k = 0; k < D; k++) {
        float4 a  = *(const float4*)&su[k * KP + b0];
        float4 v  = *(const float4*)&sc[k * KP + c0];
        float av[4] = {a.x, a.y, a.z, a.w};
        float vv[4] = {v.x, v.y, v.z, v.w};
#pragma unroll
        for (int i = 0; i < 4; i++)
#pragma unroll
            for (int j = 0; j < 4; j++) acc[i][j] += av[i] * vv[j];
    }

#pragma unroll
    for (int i = 0; i < 4; i++) {
        const int b = bbase + b0 + i;
        const int gc = cbase + c0;
        if (gc + 3 < NC) {
            *(float4*)&out[(size_t)b * NC + gc] =
                make_float4(acc[i][0], acc[i][1], acc[i][2], acc[i][3]);
        } else {
#pragma unroll
            for (int q = 0; q < 4; q++)
                if (gc + q < NC) out[(size_t)b * NC + gc + q] = acc[i][q];
        }
    }
}

// ---------------------------------------------------------------------------
extern "C" void kernel_launch(void* const* d_in, const int* in_sizes, int n_in,
                              void* d_out, int out_size) {
    const int*   stories    = (const int*)d_in[0];
    const int*   queries    = (const int*)d_in[1];
    const int*   candidates = (const int*)d_in[2];
    const float* A_tab      = (const float*)d_in[3];
    const float* W_tab      = (const float*)d_in[4];
    const float* H_w        = (const float*)d_in[5];
    float*       out        = (float*)d_out;

    const int hops_smem = (M * D + D * HW_PITCH + D + M + HOP_THREADS) * sizeof(float);
    const int gemm_smem = 2 * D * KP * sizeof(float);
    cudaFuncSetAttribute(hops_kernel, cudaFuncAttributeMaxDynamicSharedMemorySize, hops_smem);
    cudaFuncSetAttribute(gemm_kernel, cudaFuncAttributeMaxDynamicSharedMemorySize, gemm_smem);

    // 8 warp-rows per 256-thread block
    const int gather_blocks = (ROWS_TOTAL + 7) / 8;
    gather_all_kernel<<<gather_blocks, 256>>>(stories, queries, candidates, A_tab, W_tab);
    hops_kernel<<<B, HOP_THREADS, hops_smem>>>(H_w);

    dim3 ggrid((NC + BNT - 1) / BNT, B / BMT);   // 157 x 2
    gemm_kernel<<<ggrid, 256, gemm_smem>>>(out);
}

// round 7
// speedup vs baseline: 1.7015x; 1.0005x over previous
#include <cuda_runtime.h>

#define B   128
#define M   200
#define S   20
#define D   128
#define NC  10000
#define CL  10
#define HOPS 3

// Scratch (no cudaMalloc allowed)
__device__ float g_m[B * M * D];      // 13.1 MB: memory encodings
__device__ float g_u[B * D];          // query state (b-major, hops input)
__device__ float g_uT[D * B];         // query state transposed (gemm A operand)
__device__ float g_cand[NC * D];      // candidate sums

// ---------------------------------------------------------------------------
// packed f32x2 helpers (FFMA2 path — double-rate fp32, PTX-only)
// ---------------------------------------------------------------------------
__device__ __forceinline__ unsigned long long pack2(float lo, float hi) {
    unsigned long long r;
    asm("mov.b64 %0, {%1, %2};" : "=l"(r) : "f"(lo), "f"(hi));
    return r;
}
__device__ __forceinline__ void unpack2(unsigned long long p, float& lo, float& hi) {
    asm("mov.b64 {%0, %1}, %2;" : "=f"(lo), "=f"(hi) : "l"(p));
}
__device__ __forceinline__ unsigned long long fma2(unsigned long long a,
                                                   unsigned long long b,
                                                   unsigned long long c) {
    unsigned long long d;
    asm("fma.rn.f32x2 %0, %1, %2, %3;" : "=l"(d) : "l"(a), "l"(b), "l"(c));
    return d;
}

// ---------------------------------------------------------------------------
// Kernel 1: warp-per-row gathers (unchanged from R6: 27.6us, near traffic floor)
// ---------------------------------------------------------------------------
#define ROWS_TOTAL (B * M + B + NC)

template <int N>
__device__ __forceinline__ void gather_row(const int* __restrict__ idxp,
                                           const float* __restrict__ tab,
                                           float* __restrict__ dst,
                                           int lane) {
    int myidx = (lane < N) ? idxp[lane] : 0;
    float4 acc = make_float4(0.f, 0.f, 0.f, 0.f);
#pragma unroll
    for (int s = 0; s < N; s++) {
        int idx = __shfl_sync(0xffffffffu, myidx, s);
        if (idx != 0) {
            float4 v = *(const float4*)(tab + (size_t)idx * D + lane * 4);
            acc.x += v.x; acc.y += v.y; acc.z += v.z; acc.w += v.w;
        }
    }
    *(float4*)(dst + lane * 4) = acc;
}

__global__ void gather_all_kernel(const int* __restrict__ stories,
                                  const int* __restrict__ queries,
                                  const int* __restrict__ candidates,
                                  const float* __restrict__ A,
                                  const float* __restrict__ W) {
    const int row  = (blockIdx.x * blockDim.x + threadIdx.x) >> 5;
    const int lane = threadIdx.x & 31;
    if (row >= ROWS_TOTAL) return;

    if (row < B * M) {
        gather_row<S>(stories + (size_t)row * S, A, g_m + (size_t)row * D, lane);
    } else if (row < B * M + B) {
        const int b = row - B * M;
        gather_row<S>(queries + (size_t)b * S, A, g_u + (size_t)b * D, lane);
    } else {
        const int c = row - (B * M + B);
        gather_row<CL>(candidates + (size_t)c * CL, W, g_cand + (size_t)c * D, lane);
    }
}

// ---------------------------------------------------------------------------
// Kernel 2: 3 attention hops. Warp-shuffle softmax reductions (7 syncs/hop vs
// ~20), and o-phase / Hw-matvec split across all 256 threads (2x parallelism).
// ---------------------------------------------------------------------------
#define HW_PITCH 129
#define HOP_THREADS 256

__global__ void hops_kernel(const float* __restrict__ Hw) {
    extern __shared__ float smem[];
    float* sm_m   = smem;                        // M*D
    float* sm_h   = sm_m + M * D;                // D*HW_PITCH
    float* sm_u   = sm_h + D * HW_PITCH;         // D
    float* sm_dot = sm_u + D;                    // M
    float* sm_po  = sm_dot + M;                  // 256 (o partials)
    float* sm_ph  = sm_po + HOP_THREADS;         // 256 (h partials)
    float* sm_red = sm_ph + HOP_THREADS;         // 16

    const int b  = blockIdx.x;
    const int t  = threadIdx.x;
    const int warp = t >> 5, lane = t & 31;

    {
        const float4* gm4 = (const float4*)(g_m + (size_t)b * M * D);
        float4* sm4 = (float4*)sm_m;
        for (int i = t; i < M * D / 4; i += HOP_THREADS) sm4[i] = gm4[i];
        for (int i = t; i < D * D; i += HOP_THREADS) {
            int d = i >> 7, k = i & 127;
            sm_h[d * HW_PITCH + k] = Hw[i];
        }
        if (t < D) sm_u[t] = g_u[b * D + t];
    }
    __syncthreads();

    for (int hop = 0; hop < HOPS; hop++) {
        // ---- dotted[mm] = <m[mm], u> : warp per row
        for (int mm = warp; mm < M; mm += HOP_THREADS / 32) {
            const float* row = sm_m + mm * D;
            float s = 0.f;
#pragma unroll
            for (int k = lane; k < D; k += 32) s += row[k] * sm_u[k];
#pragma unroll
            for (int off = 16; off; off >>= 1)
                s += __shfl_xor_sync(0xffffffffu, s, off);
            if (lane == 0) sm_dot[mm] = s;
        }
        __syncthreads();

        // ---- softmax max (warp shuffle + 8-wide cross-warp)
        float v = (t < M) ? sm_dot[t] : -1e30f;
#pragma unroll
        for (int off = 16; off; off >>= 1)
            v = fmaxf(v, __shfl_xor_sync(0xffffffffu, v, off));
        if (lane == 0) sm_red[warp] = v;
        __syncthreads();
        if (t == 0) {
            float mx = sm_red[0];
#pragma unroll
            for (int w = 1; w < 8; w++) mx = fmaxf(mx, sm_red[w]);
            sm_red[8] = mx;
        }
        __syncthreads();
        const float mx = sm_red[8];

        // ---- exp + sum
        float e = 0.f;
        if (t < M) { e = __expf(sm_dot[t] - mx); sm_dot[t] = e; }
        float sv = e;
#pragma unroll
        for (int off = 16; off; off >>= 1)
            sv += __shfl_xor_sync(0xffffffffu, sv, off);
        if (lane == 0) sm_red[warp] = sv;
        __syncthreads();
        if (t == 0) {
            float su = 0.f;
#pragma unroll
            for (int w = 0; w < 8; w++) su += sm_red[w];
            sm_red[9] = 1.f / su;
        }
        __syncthreads();
        const float inv = sm_red[9];

        // ---- o partial (half-block splits mm range) + h partial (splits k)
        {
            const int half = t >> 7;       // 0 or 1
            const int d    = t & 127;
            float o = 0.f;
            const int m0 = half * (M / 2), m1 = m0 + (M / 2);
            for (int mm = m0; mm < m1; mm++)
                o += sm_dot[mm] * sm_m[mm * D + d];
            sm_po[t] = o;

            float h = 0.f;
            const int k0 = half * (D / 2), k1 = k0 + (D / 2);
            const float* hr = sm_h + d * HW_PITCH;
#pragma unroll 8
            for (int k = k0; k < k1; k++) h += hr[k] * sm_u[k];
            sm_ph[t] = h;
        }
        __syncthreads();

        if (t < D) {
            float o = (sm_po[t] + sm_po[t + 128]) * inv;
            float h = sm_ph[t] + sm_ph[t + 128];
            sm_u[t] = tanhf(h + o);
        }
        __syncthreads();
    }
    if (t < D) g_uT[t * B + b] = sm_u[t];   // transposed for GEMM A-stage
}

// ---------------------------------------------------------------------------
// Kernel 3: logits = u @ cand^T. 64x64 tiles, packed f32x2 FMA inner loop
// (8 FFMA2 instead of 16 FFMA per k per thread -> FMA pipe work halves).
// ---------------------------------------------------------------------------
#define BMT 64
#define BNT 64
#define KP  68    // smem pitch (floats): mult of 4 (float4), not mult of 32

__global__ void gemm_kernel(float* __restrict__ out) {
    extern __shared__ float sm[];
    float* su = sm;             // su[k*KP + b]
    float* sc = sm + D * KP;    // sc[k*KP + c]
    const int t = threadIdx.x;
    const int cbase = blockIdx.x * BNT;
    const int bbase = blockIdx.y * BMT;

    for (int i = t; i < BMT * D; i += 256) {
        int k = i >> 6, b = i & 63;
        su[k * KP + b] = g_uT[k * B + bbase + b];
    }
    for (int i = t; i < BNT * D; i += 256) {
        int c = i >> 7, k = i & 127;
        int gc = cbase + c;
        sc[k * KP + c] = (gc < NC) ? g_cand[(size_t)gc * D + k] : 0.f;
    }
    __syncthreads();

    const int tx = t & 15, ty = t >> 4;
    const int b0 = ty * 4, c0 = tx * 4;
    unsigned long long acc[4][2] = {};   // packed f32x2 accumulators (+0 bits)

#pragma unroll 8
    for (int k = 0; k < D; k++) {
        float4 a = *(const float4*)&su[k * KP + b0];
        float4 v = *(const float4*)&sc[k * KP + c0];
        unsigned long long v0 = pack2(v.x, v.y);
        unsigned long long v1 = pack2(v.z, v.w);
        unsigned long long a0 = pack2(a.x, a.x);
        unsigned long long a1 = pack2(a.y, a.y);
        unsigned long long a2 = pack2(a.z, a.z);
        unsigned long long a3 = pack2(a.w, a.w);
        acc[0][0] = fma2(a0, v0, acc[0][0]); acc[0][1] = fma2(a0, v1, acc[0][1]);
        acc[1][0] = fma2(a1, v0, acc[1][0]); acc[1][1] = fma2(a1, v1, acc[1][1]);
        acc[2][0] = fma2(a2, v0, acc[2][0]); acc[2][1] = fma2(a2, v1, acc[2][1]);
        acc[3][0] = fma2(a3, v0, acc[3][0]); acc[3][1] = fma2(a3, v1, acc[3][1]);
    }

#pragma unroll
    for (int i = 0; i < 4; i++) {
        float r0, r1, r2, r3;
        unpack2(acc[i][0], r0, r1);
        unpack2(acc[i][1], r2, r3);
        const int b = bbase + b0 + i;
        const int gc = cbase + c0;
        if (gc + 3 < NC) {
            *(float4*)&out[(size_t)b * NC + gc] = make_float4(r0, r1, r2, r3);
        } else {
            float rr[4] = {r0, r1, r2, r3};
#pragma unroll
            for (int q = 0; q < 4; q++)
                if (gc + q < NC) out[(size_t)b * NC + gc + q] = rr[q];
        }
    }
}

// ---------------------------------------------------------------------------
extern "C" void kernel_launch(void* const* d_in, const int* in_sizes, int n_in,
                              void* d_out, int out_size) {
    const int*   stories    = (const int*)d_in[0];
    const int*   queries    = (const int*)d_in[1];
    const int*   candidates = (const int*)d_in[2];
    const float* A_tab      = (const float*)d_in[3];
    const float* W_tab      = (const float*)d_in[4];
    const float* H_w        = (const float*)d_in[5];
    float*       out        = (float*)d_out;

    const int hops_smem = (M * D + D * HW_PITCH + D + M + 2 * HOP_THREADS + 16) * sizeof(float);
    const int gemm_smem = 2 * D * KP * sizeof(float);
    cudaFuncSetAttribute(hops_kernel, cudaFuncAttributeMaxDynamicSharedMemorySize, hops_smem);
    cudaFuncSetAttribute(gemm_kernel, cudaFuncAttributeMaxDynamicSharedMemorySize, gemm_smem);

    const int gather_blocks = (ROWS_TOTAL + 7) / 8;
    gather_all_kernel<<<gather_blocks, 256>>>(stories, queries, candidates, A_tab, W_tab);
    hops_kernel<<<B, HOP_THREADS, hops_smem>>>(H_w);

    dim3 ggrid((NC + BNT - 1) / BNT, B / BMT);   // 157 x 2
    gemm_kernel<<<ggrid, 256, gemm_smem>>>(out);
}